// round 15
// baseline (speedup 1.0000x reference)
#include <cuda_runtime.h>
#include <cstdint>
#include <math.h>

#define DEVI __device__ __forceinline__

static constexpr int BDIM  = 4096;
static constexpr int INDIM = 1024;
static constexpr int HDIM  = 2048;
static constexpr int KDIM  = HDIM + INDIM;        // 3072
static constexpr int MT  = 128;                   // CTA M tile
static constexpr int NG  = 64;                    // CTA N tile per gate
static constexpr int KT  = 48;                    // K chunk (6 kk-steps of 8)
static constexpr int NKK = KT / 8;                // 6
static constexpr int NCHUNK = KDIM / KT;          // 64
static constexpr int STAGES = 3;
static constexpr int A_BYTES   = MT * KT * 4;     // 24576 (frag-major A stage)
static constexpr int B_BYTES   = 4 * NG * KT * 4; // 49152 (frag-major B stage)
static constexpr int STG_BYTES = A_BYTES + B_BYTES;   // 73728
static constexpr int MBAR_OFF  = STAGES * STG_BYTES;  // 221184 (load mbars; cons at +24)
static constexpr int SMEM_TOTAL = MBAR_OFF + 64;      // 221248
static constexpr int NTHR = 256;

// fragment-major, tf32-rounded scratch (device globals: allocation-free)
// g_A: [mblk 32][chunk 64][kk 6][mfrag 8][lane 32][4 floats {a0,a1,a2,a3}]
// g_W: [nblk 32][chunk 64][kk 6][gate 4][wn 4][lane 32][4 floats {b0,b1,b0',b1'}]
__device__ __align__(1024) float g_A[(size_t)BDIM * KDIM];
__device__ __align__(1024) float g_W[(size_t)4 * HDIM * KDIM];

static constexpr int A_CHUNK4 = NKK * 8 * 32;        // 1536 float4 per chunk
static constexpr int B_CHUNK4 = NKK * 4 * 4 * 32;    // 3072 float4 per chunk
static constexpr int A_PER_MBLK4 = NCHUNK * A_CHUNK4;   // 98304
static constexpr int B_PER_NBLK4 = NCHUNK * B_CHUNK4;   // 196608
static constexpr int A_TOT4 = BDIM * KDIM / 4;          // 3145728
static constexpr int B_TOT4 = 4 * HDIM * KDIM / 4;      // 6291456

// ---------------- helpers ----------------
DEVI uint32_t smem_u32(const void* p) {
    uint32_t a;
    asm("{ .reg .u64 t; cvta.to.shared.u64 t, %1; cvt.u32.u64 %0, t; }" : "=r"(a) : "l"(p));
    return a;
}
DEVI float to_tf32(float x) {
    uint32_t u;
    asm("cvt.rna.tf32.f32 %0, %1;" : "=r"(u) : "f"(x));
    return __uint_as_float(u);
}
DEVI void mbar_init(uint32_t a, uint32_t cnt) {
    asm volatile("mbarrier.init.shared.b64 [%0], %1;" :: "r"(a), "r"(cnt) : "memory");
}
DEVI void mbar_expect_tx(uint32_t a, uint32_t tx) {
    asm volatile("mbarrier.arrive.expect_tx.shared.b64 _, [%0], %1;"
                 :: "r"(a), "r"(tx) : "memory");
}
DEVI void mbar_arrive(uint32_t a) {
    asm volatile("mbarrier.arrive.release.cta.shared::cta.b64 _, [%0];"
                 :: "r"(a) : "memory");
}
DEVI void mbar_wait(uint32_t a, uint32_t parity) {
    asm volatile(
        "{\n\t.reg .pred P;\n"
        "WL%=:\n\t"
        "mbarrier.try_wait.parity.acquire.cta.shared::cta.b64 P, [%0], %1, 0x989680;\n\t"
        "@P bra WD%=;\n\t"
        "bra WL%=;\n"
        "WD%=:\n\t}"
        :: "r"(a), "r"(parity) : "memory");
}
DEVI void bulk_g2s(uint32_t dst, const void* src, uint32_t bytes, uint32_t mbar) {
    asm volatile(
        "cp.async.bulk.shared::cluster.global.mbarrier::complete_tx::bytes "
        "[%0], [%1], %2, [%3];"
        :: "r"(dst), "l"(src), "r"(bytes), "r"(mbar) : "memory");
}
DEVI void fence_async_proxy() { asm volatile("fence.proxy.async.shared::cta;" ::: "memory"); }

struct U4 { uint32_t x, y, z, w; };
template <int IMM>
DEVI U4 lds128i(uint32_t a) {
    U4 v;
    asm("ld.shared.v4.u32 {%0,%1,%2,%3}, [%4+%5];"
        : "=r"(v.x), "=r"(v.y), "=r"(v.z), "=r"(v.w) : "r"(a), "n"(IMM));
    return v;
}
DEVI void mma8(float* d, U4 a, uint32_t b0, uint32_t b1) {
    asm("mma.sync.aligned.m16n8k8.row.col.f32.tf32.tf32.f32 "
        "{%0,%1,%2,%3}, {%4,%5,%6,%7}, {%8,%9}, {%0,%1,%2,%3};"
        : "+f"(d[0]), "+f"(d[1]), "+f"(d[2]), "+f"(d[3])
        : "r"(a.x), "r"(a.y), "r"(a.z), "r"(a.w), "r"(b0), "r"(b1));
}
DEVI float sigmoidf_(float x) { return __fdividef(1.0f, 1.0f + __expf(-x)); }
DEVI float tanhf_(float x)    { return 2.0f * sigmoidf_(2.0f * x) - 1.0f; }

// ------------- merged prep: tf32-round + gather into fragment-major order -------------
__global__ void prep_all(const float* __restrict__ x,  const float* __restrict__ ph,
                         const float* __restrict__ Wi, const float* __restrict__ Wf,
                         const float* __restrict__ Wo, const float* __restrict__ Wc) {
    const int total = A_TOT4 + B_TOT4;               // 9437184 float4
    for (int i = blockIdx.x * blockDim.x + threadIdx.x; i < total;
         i += gridDim.x * blockDim.x) {
        if (i < A_TOT4) {
            const int mblk  = i / A_PER_MBLK4;
            const int r     = i - mblk * A_PER_MBLK4;    // < 98304
            const int chunk = r / A_CHUNK4;              // 0..63
            const int t     = r - chunk * A_CHUNK4;      // < 1536
            const int kk    = t >> 8;                    // 0..5
            const int mfrag = (t >> 5) & 7;
            const int lane  = t & 31;
            const int q   = lane >> 2;
            const int cid = lane & 3;
            const int row = mblk * 128 + mfrag * 16 + q;
            const int k   = chunk * KT + kk * 8 + cid;
            float a0, a1, a2, a3;
            if (k < HDIM) {
                a0 = ph[(size_t)row * HDIM + k];
                a1 = ph[(size_t)(row + 8) * HDIM + k];
                a2 = ph[(size_t)row * HDIM + k + 4];
                a3 = ph[(size_t)(row + 8) * HDIM + k + 4];
            } else {
                const int kx = k - HDIM;
                a0 = x[(size_t)row * INDIM + kx];
                a1 = x[(size_t)(row + 8) * INDIM + kx];
                a2 = x[(size_t)row * INDIM + kx + 4];
                a3 = x[(size_t)(row + 8) * INDIM + kx + 4];
            }
            ((float4*)g_A)[i] = make_float4(to_tf32(a0), to_tf32(a1),
                                            to_tf32(a2), to_tf32(a3));
        } else {
            const int j = i - A_TOT4;
            const int nblk  = j / B_PER_NBLK4;
            const int r     = j - nblk * B_PER_NBLK4;    // < 196608
            const int chunk = r / B_CHUNK4;              // 0..63
            const int t     = r - chunk * B_CHUNK4;      // < 3072
            const int kk    = t >> 9;                    // 0..5
            const int u     = t & 511;
            const int gate = u >> 7;
            const int wn   = (u >> 5) & 3;
            const int lane = u & 31;
            const int q   = lane >> 2;
            const int cid = lane & 3;
            const int ncol = nblk * 64 + wn * 16 + q;    // nt=0 col; nt=1 is +8
            const int k    = chunk * KT + kk * 8 + cid;
            const float* W = (gate == 0) ? Wi : (gate == 1) ? Wf
                           : (gate == 2) ? Wo : Wc;
            const float b0 = W[(size_t)ncol * KDIM + k];
            const float b1 = W[(size_t)ncol * KDIM + k + 4];
            const float b2 = W[(size_t)(ncol + 8) * KDIM + k];
            const float b3 = W[(size_t)(ncol + 8) * KDIM + k + 4];
            ((float4*)g_W)[j] = make_float4(to_tf32(b0), to_tf32(b1),
                                            to_tf32(b2), to_tf32(b3));
        }
    }
}

// -- main fused LSTM GEMM (mma.sync tf32, bulk staging, barrier-free chunk loop) --
__global__ __launch_bounds__(NTHR, 1)
void lstm_main(const float* __restrict__ prev_c, float* __restrict__ out) {
    extern __shared__ char smem[];
    const uint32_t sb = smem_u32(smem);
    const int tid  = threadIdx.x;
    const int lane = tid & 31;
    const int wid  = tid >> 5;
    const int warp_m = wid & 1;        // 2 warps over M (64 rows each, m_frags=4)
    const int warp_n = wid >> 1;       // 4 warps over N (16 cols/gate, n_frags=2/gate)
    const int q   = lane >> 2;         // 0..7
    const int cid = lane & 3;          // 0..3
    const int m0 = blockIdx.x * MT;
    const int n0 = blockIdx.y * NG;

    // contiguous per-chunk slabs in frag-major scratch
    const float* a_src = g_A + (size_t)blockIdx.x * (A_PER_MBLK4 * 4);
    const float* b_src = g_W + (size_t)blockIdx.y * (B_PER_NBLK4 * 4);

    const uint32_t load_mb = sb + MBAR_OFF;        // 3 x 8B
    const uint32_t cons_mb = sb + MBAR_OFF + 24;   // 3 x 8B

    if (tid == 0) {
#pragma unroll
        for (int s = 0; s < STAGES; s++) {
            mbar_init(load_mb + 8 * s, 1);
            mbar_init(cons_mb + 8 * s, 8);         // one arrive per warp
        }
    }
    __syncthreads();

    auto issue_stage = [&](int chunk, int s) {
        const uint32_t mb = load_mb + 8 * s;
        const uint32_t so = sb + (uint32_t)(s * STG_BYTES);
        mbar_expect_tx(mb, STG_BYTES);
        bulk_g2s(so,           a_src + (size_t)chunk * (A_CHUNK4 * 4), A_BYTES, mb);
        bulk_g2s(so + A_BYTES, b_src + (size_t)chunk * (B_CHUNK4 * 4), B_BYTES, mb);
    };

    // prologue: stages 0,1 in flight (first uses — no consumer wait needed)
    if (tid == 0) { issue_stage(0, 0); issue_stage(1, 1); }

    // ---- fragment bases ----
    //   A frag (kk, mt): ca + kk*4096 + mt*512      (warp_m selects mfrag half)
    //   B quad (kk, g):  cb + kk*8192 + g*2048      (warp_n selects wn block)
    const uint32_t A0 = sb + (uint32_t)(warp_m * 2048 + lane * 16);
    const uint32_t B0 = sb + A_BYTES + (uint32_t)(warp_n * 512 + lane * 16);

    float acc[4][4][2][4];             // [gate][mt][nt][e]
#pragma unroll
    for (int g = 0; g < 4; g++)
#pragma unroll
        for (int mt = 0; mt < 4; mt++)
#pragma unroll
            for (int nt = 0; nt < 2; nt++)
#pragma unroll
                for (int e = 0; e < 4; e++) acc[g][mt][nt][e] = 0.0f;

    U4 af[2][4];      // [buf][mt]
    U4 bq[2][4];      // [buf][gate]  (x,y = nt0 pair; z,w = nt1 pair)

    auto load_frags = [&](int buf, uint32_t ax, uint32_t bx) {
        af[buf][0] = lds128i<0>(ax);    af[buf][1] = lds128i<512>(ax);
        af[buf][2] = lds128i<1024>(ax); af[buf][3] = lds128i<1536>(ax);
        bq[buf][0] = lds128i<0>(bx);    bq[buf][1] = lds128i<2048>(bx);
        bq[buf][2] = lds128i<4096>(bx); bq[buf][3] = lds128i<6144>(bx);
    };

    // wait for chunk 0 and prime its kk=0 fragments into buf 0
    mbar_wait(load_mb + 0, 0);
    load_frags(0, A0, B0);

    for (int c = 0; c < NCHUNK; c++) {
        const int s = c % STAGES;
        // producer (tid0 only): re-issue into stage (c+2)%3 == (c-1)%3 once all
        // warps have arrived for chunk c-1 (their fences order reads vs TMA writes)
        if (tid == 0 && c + 2 < NCHUNK) {
            if (c >= 1)
                mbar_wait(cons_mb + 8 * ((c - 1) % STAGES),
                          (uint32_t)(((c - 1) / STAGES) & 1));
            issue_stage(c + 2, (c + 2) % STAGES);
        }

        const uint32_t so = (uint32_t)(s * STG_BYTES);
        const uint32_t ca = A0 + so;
        const uint32_t cb = B0 + so;
        const uint32_t ns = (uint32_t)(((c + 1) % STAGES) * STG_BYTES);

#pragma unroll
        for (int kk = 0; kk < NKK; kk++) {
            const int cur = kk & 1;
            if (kk == 1 && c + 1 < NCHUNK) {
                // mid-chunk: wait for next chunk's bulk copy (issued at c-1)
                mbar_wait(load_mb + 8 * ((c + 1) % STAGES),
                          (uint32_t)(((c + 1) / STAGES) & 1));
            }
            if (kk + 1 < NKK) {
                load_frags(cur ^ 1, ca + (kk + 1) * 4096, cb + (kk + 1) * 8192);
            } else if (c + 1 < NCHUNK) {
                // prefetch next chunk's kk=0 fragments across the boundary
                load_frags(cur ^ 1, A0 + ns, B0 + ns);
            }
#pragma unroll
            for (int g = 0; g < 4; g++)
#pragma unroll
                for (int mt = 0; mt < 4; mt++) {
                    mma8(acc[g][mt][0], af[cur][mt], bq[cur][g].x, bq[cur][g].y);
                    mma8(acc[g][mt][1], af[cur][mt], bq[cur][g].z, bq[cur][g].w);
                }
        }
        // this warp is done reading stage s: fence generic reads, then arrive
        fence_async_proxy();
        if (lane == 0) mbar_arrive(cons_mb + 8 * s);
    }

    // -------- fused LSTM epilogue (register-wise across gates) --------
#pragma unroll
    for (int mt = 0; mt < 4; mt++)
#pragma unroll
        for (int h = 0; h < 2; h++) {
            const int b = m0 + warp_m * 64 + mt * 16 + q + 8 * h;
            const float* pc = prev_c + (size_t)b * HDIM;
            float* oh = out + (size_t)b * HDIM;
            float* oc = out + (size_t)(BDIM + b) * HDIM;
#pragma unroll
            for (int nt = 0; nt < 2; nt++) {
                const int n = n0 + warp_n * 16 + nt * 8 + 2 * cid;
                float2 pcv = *(const float2*)(pc + n);
                float hv[2], cv[2];
#pragma unroll
                for (int e = 0; e < 2; e++) {
                    const float gi = acc[0][mt][nt][2 * h + e];
                    const float gf = acc[1][mt][nt][2 * h + e];
                    const float go = acc[2][mt][nt][2 * h + e];
                    const float gc = acc[3][mt][nt][2 * h + e];
                    const float iv = sigmoidf_(gi);
                    const float fv = sigmoidf_(gf);
                    const float ov = sigmoidf_(go);
                    const float ct = tanhf_(gc);
                    const float pcx = (e == 0) ? pcv.x : pcv.y;
                    const float cc = fv * pcx + iv * ct;
                    cv[e] = cc;
                    hv[e] = ov * tanhf_(cc);
                }
                *(float2*)(oh + n) = make_float2(hv[0], hv[1]);
                *(float2*)(oc + n) = make_float2(cv[0], cv[1]);
            }
        }
}

// ---------------- host launch ----------------
extern "C" void kernel_launch(void* const* d_in, const int* in_sizes, int n_in,
                              void* d_out, int out_size) {
    const float* x      = (const float*)d_in[0];
    const float* prev_h = (const float*)d_in[1];
    const float* prev_c = (const float*)d_in[2];
    const float* Wi     = (const float*)d_in[3];
    const float* Wf     = (const float*)d_in[4];
    const float* Wo     = (const float*)d_in[5];
    const float* Wc     = (const float*)d_in[6];
    float* out = (float*)d_out;

    prep_all<<<9216, 256>>>(x, prev_h, Wi, Wf, Wo, Wc);

    static bool attr_set = false;
    if (!attr_set) {
        cudaFuncSetAttribute(lstm_main, cudaFuncAttributeMaxDynamicSharedMemorySize,
                             SMEM_TOTAL);
        attr_set = true;
    }
    dim3 grid(BDIM / MT, HDIM / NG);   // (32, 32); x-fast -> CTAs sharing weights co-resident
    lstm_main<<<grid, NTHR, SMEM_TOTAL>>>(prev_c, out);
    (void)in_sizes; (void)n_in; (void)out_size;
}

// round 16
// speedup vs baseline: 1.0190x; 1.0190x over previous
#include <cuda_runtime.h>
#include <cstdint>
#include <math.h>

#define DEVI __device__ __forceinline__

static constexpr int BDIM  = 4096;
static constexpr int INDIM = 1024;
static constexpr int HDIM  = 2048;
static constexpr int KDIM  = HDIM + INDIM;        // 3072
static constexpr int MT  = 128;                   // CTA M tile
static constexpr int NG  = 64;                    // CTA N tile per gate
static constexpr int KT  = 48;                    // K chunk (6 kk-steps of 8)
static constexpr int NKK = KT / 8;                // 6
static constexpr int NCHUNK = KDIM / KT;          // 64
static constexpr int STAGES = 3;
static constexpr int A_BYTES   = MT * KT * 4;     // 24576 (frag-major A stage)
static constexpr int B_BYTES   = 4 * NG * KT * 4; // 49152 (frag-major B stage)
static constexpr int STG_BYTES = A_BYTES + B_BYTES;   // 73728
static constexpr int MBAR_OFF  = STAGES * STG_BYTES;  // 221184
static constexpr int SMEM_TOTAL = MBAR_OFF + 64;      // 221248
static constexpr int NTHR = 256;

// fragment-major, tf32-rounded scratch (device globals: allocation-free)
// g_A: [mblk 32][chunk 64][kk 6][mfrag 8][lane 32][4 floats {a0,a1,a2,a3}]
// g_W: [nblk 32][chunk 64][kk 6][gate 4][wn 4][lane 32][4 floats {b0,b1,b0',b1'}]
__device__ __align__(1024) float g_A[(size_t)BDIM * KDIM];
__device__ __align__(1024) float g_W[(size_t)4 * HDIM * KDIM];

static constexpr int A_CHUNK4 = NKK * 8 * 32;        // 1536 float4 per chunk
static constexpr int B_CHUNK4 = NKK * 4 * 4 * 32;    // 3072 float4 per chunk
static constexpr int A_PER_MBLK4 = NCHUNK * A_CHUNK4;   // 98304
static constexpr int B_PER_NBLK4 = NCHUNK * B_CHUNK4;   // 196608
static constexpr int A_TOT4 = BDIM * KDIM / 4;          // 3145728
static constexpr int B_TOT4 = 4 * HDIM * KDIM / 4;      // 6291456

// ---------------- helpers ----------------
DEVI uint32_t smem_u32(const void* p) {
    uint32_t a;
    asm("{ .reg .u64 t; cvta.to.shared.u64 t, %1; cvt.u32.u64 %0, t; }" : "=r"(a) : "l"(p));
    return a;
}
DEVI float to_tf32(float x) {
    uint32_t u;
    asm("cvt.rna.tf32.f32 %0, %1;" : "=r"(u) : "f"(x));
    return __uint_as_float(u);
}
DEVI void mbar_init(uint32_t a, uint32_t cnt) {
    asm volatile("mbarrier.init.shared.b64 [%0], %1;" :: "r"(a), "r"(cnt) : "memory");
}
DEVI void mbar_expect_tx(uint32_t a, uint32_t tx) {
    asm volatile("mbarrier.arrive.expect_tx.shared.b64 _, [%0], %1;"
                 :: "r"(a), "r"(tx) : "memory");
}
DEVI void mbar_wait(uint32_t a, uint32_t parity) {
    asm volatile(
        "{\n\t.reg .pred P;\n"
        "WL%=:\n\t"
        "mbarrier.try_wait.parity.acquire.cta.shared::cta.b64 P, [%0], %1, 0x989680;\n\t"
        "@P bra WD%=;\n\t"
        "bra WL%=;\n"
        "WD%=:\n\t}"
        :: "r"(a), "r"(parity) : "memory");
}
DEVI void bulk_g2s(uint32_t dst, const void* src, uint32_t bytes, uint32_t mbar) {
    asm volatile(
        "cp.async.bulk.shared::cluster.global.mbarrier::complete_tx::bytes "
        "[%0], [%1], %2, [%3];"
        :: "r"(dst), "l"(src), "r"(bytes), "r"(mbar) : "memory");
}
DEVI void fence_async_proxy() { asm volatile("fence.proxy.async.shared::cta;" ::: "memory"); }

struct U4 { uint32_t x, y, z, w; };
template <int IMM>
DEVI U4 lds128i(uint32_t a) {
    U4 v;
    asm("ld.shared.v4.u32 {%0,%1,%2,%3}, [%4+%5];"
        : "=r"(v.x), "=r"(v.y), "=r"(v.z), "=r"(v.w) : "r"(a), "n"(IMM));
    return v;
}
DEVI void mma8(float* d, U4 a, uint32_t b0, uint32_t b1) {
    asm("mma.sync.aligned.m16n8k8.row.col.f32.tf32.tf32.f32 "
        "{%0,%1,%2,%3}, {%4,%5,%6,%7}, {%8,%9}, {%0,%1,%2,%3};"
        : "+f"(d[0]), "+f"(d[1]), "+f"(d[2]), "+f"(d[3])
        : "r"(a.x), "r"(a.y), "r"(a.z), "r"(a.w), "r"(b0), "r"(b1));
}
DEVI float sigmoidf_(float x) { return __fdividef(1.0f, 1.0f + __expf(-x)); }
DEVI float tanhf_(float x)    { return 2.0f * sigmoidf_(2.0f * x) - 1.0f; }

// ------------- merged prep: tf32-round + gather into fragment-major order -------------
__global__ void prep_all(const float* __restrict__ x,  const float* __restrict__ ph,
                         const float* __restrict__ Wi, const float* __restrict__ Wf,
                         const float* __restrict__ Wo, const float* __restrict__ Wc) {
    const int total = A_TOT4 + B_TOT4;               // 9437184 float4
    for (int i = blockIdx.x * blockDim.x + threadIdx.x; i < total;
         i += gridDim.x * blockDim.x) {
        if (i < A_TOT4) {
            const int mblk  = i / A_PER_MBLK4;
            const int r     = i - mblk * A_PER_MBLK4;    // < 98304
            const int chunk = r / A_CHUNK4;              // 0..63
            const int t     = r - chunk * A_CHUNK4;      // < 1536
            const int kk    = t >> 8;                    // 0..5
            const int mfrag = (t >> 5) & 7;
            const int lane  = t & 31;
            const int q   = lane >> 2;
            const int cid = lane & 3;
            const int row = mblk * 128 + mfrag * 16 + q;
            const int k   = chunk * KT + kk * 8 + cid;
            float a0, a1, a2, a3;
            if (k < HDIM) {
                a0 = ph[(size_t)row * HDIM + k];
                a1 = ph[(size_t)(row + 8) * HDIM + k];
                a2 = ph[(size_t)row * HDIM + k + 4];
                a3 = ph[(size_t)(row + 8) * HDIM + k + 4];
            } else {
                const int kx = k - HDIM;
                a0 = x[(size_t)row * INDIM + kx];
                a1 = x[(size_t)(row + 8) * INDIM + kx];
                a2 = x[(size_t)row * INDIM + kx + 4];
                a3 = x[(size_t)(row + 8) * INDIM + kx + 4];
            }
            ((float4*)g_A)[i] = make_float4(to_tf32(a0), to_tf32(a1),
                                            to_tf32(a2), to_tf32(a3));
        } else {
            const int j = i - A_TOT4;
            const int nblk  = j / B_PER_NBLK4;
            const int r     = j - nblk * B_PER_NBLK4;    // < 196608
            const int chunk = r / B_CHUNK4;              // 0..63
            const int t     = r - chunk * B_CHUNK4;      // < 3072
            const int kk    = t >> 9;                    // 0..5
            const int u     = t & 511;
            const int gate = u >> 7;
            const int wn   = (u >> 5) & 3;
            const int lane = u & 31;
            const int q   = lane >> 2;
            const int cid = lane & 3;
            const int ncol = nblk * 64 + wn * 16 + q;    // nt=0 col; nt=1 is +8
            const int k    = chunk * KT + kk * 8 + cid;
            const float* W = (gate == 0) ? Wi : (gate == 1) ? Wf
                           : (gate == 2) ? Wo : Wc;
            const float b0 = W[(size_t)ncol * KDIM + k];
            const float b1 = W[(size_t)ncol * KDIM + k + 4];
            const float b2 = W[(size_t)(ncol + 8) * KDIM + k];
            const float b3 = W[(size_t)(ncol + 8) * KDIM + k + 4];
            ((float4*)g_W)[j] = make_float4(to_tf32(b0), to_tf32(b1),
                                            to_tf32(b2), to_tf32(b3));
        }
    }
}

// -- main fused LSTM GEMM (mma.sync tf32, bulk staging, staggered mid-chunk waits) --
__global__ __launch_bounds__(NTHR, 1)
void lstm_main(const float* __restrict__ prev_c, float* __restrict__ out) {
    extern __shared__ char smem[];
    const uint32_t sb = smem_u32(smem);
    const int tid  = threadIdx.x;
    const int lane = tid & 31;
    const int wid  = tid >> 5;
    const int warp_m = wid & 1;        // 2 warps over M (64 rows each, m_frags=4)
    const int warp_n = wid >> 1;       // 4 warps over N (16 cols/gate, n_frags=2/gate)
    const int q   = lane >> 2;         // 0..7
    const int cid = lane & 3;          // 0..3
    const int m0 = blockIdx.x * MT;
    const int n0 = blockIdx.y * NG;

    // warps wid and wid+4 share an SMSP (wid%4): stagger their mid-chunk waits
    const int wait_kk = 1 + ((wid >> 2) & 1);    // warps 0-3: kk==1, warps 4-7: kk==2

    // contiguous per-chunk slabs in frag-major scratch
    const float* a_src = g_A + (size_t)blockIdx.x * (A_PER_MBLK4 * 4);
    const float* b_src = g_W + (size_t)blockIdx.y * (B_PER_NBLK4 * 4);

    if (tid == 0) {
#pragma unroll
        for (int s = 0; s < STAGES; s++) mbar_init(sb + MBAR_OFF + 8 * s, 1);
    }
    __syncthreads();

    auto issue_stage = [&](int chunk, int s) {
        const uint32_t mb = sb + MBAR_OFF + 8 * s;
        const uint32_t so = sb + (uint32_t)(s * STG_BYTES);
        mbar_expect_tx(mb, STG_BYTES);
        bulk_g2s(so,           a_src + (size_t)chunk * (A_CHUNK4 * 4), A_BYTES, mb);
        bulk_g2s(so + A_BYTES, b_src + (size_t)chunk * (B_CHUNK4 * 4), B_BYTES, mb);
    };

    // prologue: stages 0,1 in flight
    if (tid == 0) { issue_stage(0, 0); issue_stage(1, 1); }

    // ---- fragment bases ----
    //   A frag (kk, mt): ca + kk*4096 + mt*512      (warp_m selects mfrag half)
    //   B quad (kk, g):  cb + kk*8192 + g*2048      (warp_n selects wn block)
    const uint32_t A0 = sb + (uint32_t)(warp_m * 2048 + lane * 16);
    const uint32_t B0 = sb + A_BYTES + (uint32_t)(warp_n * 512 + lane * 16);

    float acc[4][4][2][4];             // [gate][mt][nt][e]
#pragma unroll
    for (int g = 0; g < 4; g++)
#pragma unroll
        for (int mt = 0; mt < 4; mt++)
#pragma unroll
            for (int nt = 0; nt < 2; nt++)
#pragma unroll
                for (int e = 0; e < 4; e++) acc[g][mt][nt][e] = 0.0f;

    U4 af[2][4];      // [buf][mt]
    U4 bq[2][4];      // [buf][gate]  (x,y = nt0 pair; z,w = nt1 pair)

    auto load_frags = [&](int buf, uint32_t ax, uint32_t bx) {
        af[buf][0] = lds128i<0>(ax);    af[buf][1] = lds128i<512>(ax);
        af[buf][2] = lds128i<1024>(ax); af[buf][3] = lds128i<1536>(ax);
        bq[buf][0] = lds128i<0>(bx);    bq[buf][1] = lds128i<2048>(bx);
        bq[buf][2] = lds128i<4096>(bx); bq[buf][3] = lds128i<6144>(bx);
    };

    // wait for chunk 0 and prime its kk=0 fragments into buf 0
    mbar_wait(sb + MBAR_OFF + 0, 0);
    load_frags(0, A0, B0);

    for (int c = 0; c < NCHUNK; c++) {
        const int s = c % STAGES;
        // all warps finished reading stage (c-1)%3 == (c+2)%3 before re-issue into it
        __syncthreads();
        if (tid == 0 && c + 2 < NCHUNK) {
            fence_async_proxy();
            issue_stage(c + 2, (c + 2) % STAGES);
        }

        const uint32_t so = (uint32_t)(s * STG_BYTES);
        const uint32_t ca = A0 + so;
        const uint32_t cb = B0 + so;
        const uint32_t ns = (uint32_t)(((c + 1) % STAGES) * STG_BYTES);

#pragma unroll
        for (int kk = 0; kk < NKK; kk++) {
            const int cur = kk & 1;
            if (kk == wait_kk && c + 1 < NCHUNK) {
                // staggered mid-chunk wait: partner warp on this SMSP keeps
                // the tensor pipe fed while we poll (copy issued at c-1)
                mbar_wait(sb + MBAR_OFF + 8 * ((c + 1) % STAGES),
                          (uint32_t)(((c + 1) / STAGES) & 1));
            }
            if (kk + 1 < NKK) {
                load_frags(cur ^ 1, ca + (kk + 1) * 4096, cb + (kk + 1) * 8192);
            } else if (c + 1 < NCHUNK) {
                // prefetch next chunk's kk=0 fragments across the boundary
                load_frags(cur ^ 1, A0 + ns, B0 + ns);
            }
#pragma unroll
            for (int g = 0; g < 4; g++)
#pragma unroll
                for (int mt = 0; mt < 4; mt++) {
                    mma8(acc[g][mt][0], af[cur][mt], bq[cur][g].x, bq[cur][g].y);
                    mma8(acc[g][mt][1], af[cur][mt], bq[cur][g].z, bq[cur][g].w);
                }
        }
        // next chunk starts with its kk=0 frags already in buf (NKK&1)==0
    }

    // -------- fused LSTM epilogue (register-wise across gates) --------
#pragma unroll
    for (int mt = 0; mt < 4; mt++)
#pragma unroll
        for (int h = 0; h < 2; h++) {
            const int b = m0 + warp_m * 64 + mt * 16 + q + 8 * h;
            const float* pc = prev_c + (size_t)b * HDIM;
            float* oh = out + (size_t)b * HDIM;
            float* oc = out + (size_t)(BDIM + b) * HDIM;
#pragma unroll
            for (int nt = 0; nt < 2; nt++) {
                const int n = n0 + warp_n * 16 + nt * 8 + 2 * cid;
                float2 pcv = *(const float2*)(pc + n);
                float hv[2], cv[2];
#pragma unroll
                for (int e = 0; e < 2; e++) {
                    const float gi = acc[0][mt][nt][2 * h + e];
                    const float gf = acc[1][mt][nt][2 * h + e];
                    const float go = acc[2][mt][nt][2 * h + e];
                    const float gc = acc[3][mt][nt][2 * h + e];
                    const float iv = sigmoidf_(gi);
                    const float fv = sigmoidf_(gf);
                    const float ov = sigmoidf_(go);
                    const float ct = tanhf_(gc);
                    const float pcx = (e == 0) ? pcv.x : pcv.y;
                    const float cc = fv * pcx + iv * ct;
                    cv[e] = cc;
                    hv[e] = ov * tanhf_(cc);
                }
                *(float2*)(oh + n) = make_float2(hv[0], hv[1]);
                *(float2*)(oc + n) = make_float2(cv[0], cv[1]);
            }
        }
}

// ---------------- host launch ----------------
extern "C" void kernel_launch(void* const* d_in, const int* in_sizes, int n_in,
                              void* d_out, int out_size) {
    const float* x      = (const float*)d_in[0];
    const float* prev_h = (const float*)d_in[1];
    const float* prev_c = (const float*)d_in[2];
    const float* Wi     = (const float*)d_in[3];
    const float* Wf     = (const float*)d_in[4];
    const float* Wo     = (const float*)d_in[5];
    const float* Wc     = (const float*)d_in[6];
    float* out = (float*)d_out;

    prep_all<<<9216, 256>>>(x, prev_h, Wi, Wf, Wo, Wc);

    static bool attr_set = false;
    if (!attr_set) {
        cudaFuncSetAttribute(lstm_main, cudaFuncAttributeMaxDynamicSharedMemorySize,
                             SMEM_TOTAL);
        attr_set = true;
    }
    dim3 grid(BDIM / MT, HDIM / NG);   // (32, 32); x-fast -> CTAs sharing weights co-resident
    lstm_main<<<grid, NTHR, SMEM_TOTAL>>>(prev_c, out);
    (void)in_sizes; (void)n_in; (void)out_size;
}

// round 17
// speedup vs baseline: 1.0249x; 1.0058x over previous
#include <cuda_runtime.h>
#include <cstdint>
#include <math.h>

#define DEVI __device__ __forceinline__

static constexpr int BDIM  = 4096;
static constexpr int INDIM = 1024;
static constexpr int HDIM  = 2048;
static constexpr int KDIM  = HDIM + INDIM;        // 3072
static constexpr int MT  = 128;                   // CTA M tile
static constexpr int NG  = 64;                    // CTA N tile per gate
static constexpr int KT  = 64;                    // K chunk (8 kk-steps of 8)
static constexpr int NKK = KT / 8;                // 8
static constexpr int NCHUNK = KDIM / KT;          // 48
static constexpr int STAGES = 2;
static constexpr int A_BYTES   = MT * KT * 4;     // 32768 (frag-major A stage)
static constexpr int B_BYTES   = 4 * NG * KT * 4; // 65536 (frag-major B stage)
static constexpr int STG_BYTES = A_BYTES + B_BYTES;   // 98304
static constexpr int MBAR_OFF  = STAGES * STG_BYTES;  // 196608
static constexpr int SMEM_TOTAL = MBAR_OFF + 64;      // 196672
static constexpr int NTHR = 256;

// fragment-major, tf32-rounded scratch (device globals: allocation-free)
// g_A: [mblk 32][chunk 48][kk 8][mfrag 8][lane 32][4 floats {a0,a1,a2,a3}]
// g_W: [nblk 32][chunk 48][kk 8][gate 4][wn 4][lane 32][4 floats {b0,b1,b0',b1'}]
__device__ __align__(1024) float g_A[(size_t)BDIM * KDIM];
__device__ __align__(1024) float g_W[(size_t)4 * HDIM * KDIM];

static constexpr int A_CHUNK4 = NKK * 8 * 32;        // 2048 float4 per chunk
static constexpr int B_CHUNK4 = NKK * 4 * 4 * 32;    // 4096 float4 per chunk
static constexpr int A_PER_MBLK4 = NCHUNK * A_CHUNK4;   // 98304
static constexpr int B_PER_NBLK4 = NCHUNK * B_CHUNK4;   // 196608
static constexpr int A_TOT4 = BDIM * KDIM / 4;          // 3145728
static constexpr int B_TOT4 = 4 * HDIM * KDIM / 4;      // 6291456

// ---------------- helpers ----------------
DEVI uint32_t smem_u32(const void* p) {
    uint32_t a;
    asm("{ .reg .u64 t; cvta.to.shared.u64 t, %1; cvt.u32.u64 %0, t; }" : "=r"(a) : "l"(p));
    return a;
}
DEVI float to_tf32(float x) {
    uint32_t u;
    asm("cvt.rna.tf32.f32 %0, %1;" : "=r"(u) : "f"(x));
    return __uint_as_float(u);
}
DEVI void mbar_init(uint32_t a, uint32_t cnt) {
    asm volatile("mbarrier.init.shared.b64 [%0], %1;" :: "r"(a), "r"(cnt) : "memory");
}
DEVI void mbar_expect_tx(uint32_t a, uint32_t tx) {
    asm volatile("mbarrier.arrive.expect_tx.shared.b64 _, [%0], %1;"
                 :: "r"(a), "r"(tx) : "memory");
}
DEVI void mbar_wait(uint32_t a, uint32_t parity) {
    asm volatile(
        "{\n\t.reg .pred P;\n"
        "WL%=:\n\t"
        "mbarrier.try_wait.parity.acquire.cta.shared::cta.b64 P, [%0], %1, 0x989680;\n\t"
        "@P bra WD%=;\n\t"
        "bra WL%=;\n"
        "WD%=:\n\t}"
        :: "r"(a), "r"(parity) : "memory");
}
DEVI void bulk_g2s(uint32_t dst, const void* src, uint32_t bytes, uint32_t mbar) {
    asm volatile(
        "cp.async.bulk.shared::cluster.global.mbarrier::complete_tx::bytes "
        "[%0], [%1], %2, [%3];"
        :: "r"(dst), "l"(src), "r"(bytes), "r"(mbar) : "memory");
}
DEVI void fence_async_proxy() { asm volatile("fence.proxy.async.shared::cta;" ::: "memory"); }

struct U4 { uint32_t x, y, z, w; };
template <int IMM>
DEVI U4 lds128i(uint32_t a) {
    U4 v;
    asm("ld.shared.v4.u32 {%0,%1,%2,%3}, [%4+%5];"
        : "=r"(v.x), "=r"(v.y), "=r"(v.z), "=r"(v.w) : "r"(a), "n"(IMM));
    return v;
}
DEVI void mma8(float* d, U4 a, uint32_t b0, uint32_t b1) {
    asm("mma.sync.aligned.m16n8k8.row.col.f32.tf32.tf32.f32 "
        "{%0,%1,%2,%3}, {%4,%5,%6,%7}, {%8,%9}, {%0,%1,%2,%3};"
        : "+f"(d[0]), "+f"(d[1]), "+f"(d[2]), "+f"(d[3])
        : "r"(a.x), "r"(a.y), "r"(a.z), "r"(a.w), "r"(b0), "r"(b1));
}
DEVI float sigmoidf_(float x) { return __fdividef(1.0f, 1.0f + __expf(-x)); }
DEVI float tanhf_(float x)    { return 2.0f * sigmoidf_(2.0f * x) - 1.0f; }

// ------------- merged prep: tf32-round + gather into fragment-major order -------------
__global__ void prep_all(const float* __restrict__ x,  const float* __restrict__ ph,
                         const float* __restrict__ Wi, const float* __restrict__ Wf,
                         const float* __restrict__ Wo, const float* __restrict__ Wc) {
    const int total = A_TOT4 + B_TOT4;               // 9437184 float4
    for (int i = blockIdx.x * blockDim.x + threadIdx.x; i < total;
         i += gridDim.x * blockDim.x) {
        if (i < A_TOT4) {
            const int mblk  = i / A_PER_MBLK4;
            const int r     = i - mblk * A_PER_MBLK4;    // < 98304 = 48*2048
            const int chunk = r / A_CHUNK4;              // 0..47
            const int t     = r - chunk * A_CHUNK4;      // < 2048
            const int kk    = t >> 8;                    // 0..7
            const int mfrag = (t >> 5) & 7;
            const int lane  = t & 31;
            const int q   = lane >> 2;
            const int cid = lane & 3;
            const int row = mblk * 128 + mfrag * 16 + q;
            const int k   = chunk * KT + kk * 8 + cid;
            float a0, a1, a2, a3;
            if (k < HDIM) {
                a0 = ph[(size_t)row * HDIM + k];
                a1 = ph[(size_t)(row + 8) * HDIM + k];
                a2 = ph[(size_t)row * HDIM + k + 4];
                a3 = ph[(size_t)(row + 8) * HDIM + k + 4];
            } else {
                const int kx = k - HDIM;
                a0 = x[(size_t)row * INDIM + kx];
                a1 = x[(size_t)(row + 8) * INDIM + kx];
                a2 = x[(size_t)row * INDIM + kx + 4];
                a3 = x[(size_t)(row + 8) * INDIM + kx + 4];
            }
            ((float4*)g_A)[i] = make_float4(to_tf32(a0), to_tf32(a1),
                                            to_tf32(a2), to_tf32(a3));
        } else {
            const int j = i - A_TOT4;
            const int nblk  = j / B_PER_NBLK4;
            const int r     = j - nblk * B_PER_NBLK4;    // < 196608 = 48*4096
            const int chunk = r / B_CHUNK4;              // 0..47
            const int t     = r - chunk * B_CHUNK4;      // < 4096
            const int kk    = t >> 9;                    // 0..7
            const int u     = t & 511;
            const int gate = u >> 7;
            const int wn   = (u >> 5) & 3;
            const int lane = u & 31;
            const int q   = lane >> 2;
            const int cid = lane & 3;
            const int ncol = nblk * 64 + wn * 16 + q;    // nt=0 col; nt=1 is +8
            const int k    = chunk * KT + kk * 8 + cid;
            const float* W = (gate == 0) ? Wi : (gate == 1) ? Wf
                           : (gate == 2) ? Wo : Wc;
            const float b0 = W[(size_t)ncol * KDIM + k];
            const float b1 = W[(size_t)ncol * KDIM + k + 4];
            const float b2 = W[(size_t)(ncol + 8) * KDIM + k];
            const float b3 = W[(size_t)(ncol + 8) * KDIM + k + 4];
            ((float4*)g_W)[j] = make_float4(to_tf32(b0), to_tf32(b1),
                                            to_tf32(b2), to_tf32(b3));
        }
    }
}

// -- main fused LSTM GEMM (mma.sync tf32, 2-stage bulk staging, KT=64, late waits) --
__global__ __launch_bounds__(NTHR, 1)
void lstm_main(const float* __restrict__ prev_c, float* __restrict__ out) {
    extern __shared__ char smem[];
    const uint32_t sb = smem_u32(smem);
    const int tid  = threadIdx.x;
    const int lane = tid & 31;
    const int wid  = tid >> 5;
    const int warp_m = wid & 1;        // 2 warps over M (64 rows each, m_frags=4)
    const int warp_n = wid >> 1;       // 4 warps over N (16 cols/gate, n_frags=2/gate)
    const int q   = lane >> 2;         // 0..7
    const int cid = lane & 3;          // 0..3
    const int m0 = blockIdx.x * MT;
    const int n0 = blockIdx.y * NG;

    // warps wid and wid+4 share an SMSP (wid%4): stagger their mid-chunk waits
    const int wait_kk = 5 + ((wid >> 2) & 1);    // warps 0-3: kk==5, warps 4-7: kk==6

    // contiguous per-chunk slabs in frag-major scratch
    const float* a_src = g_A + (size_t)blockIdx.x * (A_PER_MBLK4 * 4);
    const float* b_src = g_W + (size_t)blockIdx.y * (B_PER_NBLK4 * 4);

    if (tid == 0) {
#pragma unroll
        for (int s = 0; s < STAGES; s++) mbar_init(sb + MBAR_OFF + 8 * s, 1);
    }
    __syncthreads();

    auto issue_stage = [&](int chunk, int s) {
        const uint32_t mb = sb + MBAR_OFF + 8 * s;
        const uint32_t so = sb + (uint32_t)(s * STG_BYTES);
        mbar_expect_tx(mb, STG_BYTES);
        bulk_g2s(so,           a_src + (size_t)chunk * (A_CHUNK4 * 4), A_BYTES, mb);
        bulk_g2s(so + A_BYTES, b_src + (size_t)chunk * (B_CHUNK4 * 4), B_BYTES, mb);
    };

    // prologue: chunk 0 in flight
    if (tid == 0) issue_stage(0, 0);

    // ---- fragment bases ----
    //   A frag (kk, mt): ca + kk*4096 + mt*512      (warp_m selects mfrag half)
    //   B quad (kk, g):  cb + kk*8192 + g*2048      (warp_n selects wn block)
    const uint32_t A0 = sb + (uint32_t)(warp_m * 2048 + lane * 16);
    const uint32_t B0 = sb + A_BYTES + (uint32_t)(warp_n * 512 + lane * 16);

    float acc[4][4][2][4];             // [gate][mt][nt][e]
#pragma unroll
    for (int g = 0; g < 4; g++)
#pragma unroll
        for (int mt = 0; mt < 4; mt++)
#pragma unroll
            for (int nt = 0; nt < 2; nt++)
#pragma unroll
                for (int e = 0; e < 4; e++) acc[g][mt][nt][e] = 0.0f;

    U4 af[2][4];      // [buf][mt]
    U4 bq[2][4];      // [buf][gate]  (x,y = nt0 pair; z,w = nt1 pair)

    auto load_frags = [&](int buf, uint32_t ax, uint32_t bx) {
        af[buf][0] = lds128i<0>(ax);    af[buf][1] = lds128i<512>(ax);
        af[buf][2] = lds128i<1024>(ax); af[buf][3] = lds128i<1536>(ax);
        bq[buf][0] = lds128i<0>(bx);    bq[buf][1] = lds128i<2048>(bx);
        bq[buf][2] = lds128i<4096>(bx); bq[buf][3] = lds128i<6144>(bx);
    };

    // wait for chunk 0 and prime its kk=0 fragments into buf 0
    mbar_wait(sb + MBAR_OFF + 0, 0);
    load_frags(0, A0, B0);

    for (int c = 0; c < NCHUNK; c++) {
        const int s = c & 1;
        // all warps finished reading stage (c+1)&1 == (c-1)&1 before re-issue into it
        __syncthreads();
        if (tid == 0 && c + 1 < NCHUNK) {
            fence_async_proxy();
            issue_stage(c + 1, (c + 1) & 1);
        }

        const uint32_t so = (uint32_t)(s * STG_BYTES);
        const uint32_t ca = A0 + so;
        const uint32_t cb = B0 + so;
        const uint32_t ns = (uint32_t)(((c + 1) & 1) * STG_BYTES);

#pragma unroll
        for (int kk = 0; kk < NKK; kk++) {
            const int cur = kk & 1;
            if (kk == wait_kk && c + 1 < NCHUNK) {
                // late staggered wait: chunk c+1's copy was issued at top of this
                // chunk; ~5/8 of the chunk has elapsed, partner warp covers the poll
                mbar_wait(sb + MBAR_OFF + 8 * ((c + 1) & 1),
                          (uint32_t)(((c + 1) >> 1) & 1));
            }
            if (kk + 1 < NKK) {
                load_frags(cur ^ 1, ca + (kk + 1) * 4096, cb + (kk + 1) * 8192);
            } else if (c + 1 < NCHUNK) {
                // prefetch next chunk's kk=0 fragments across the boundary
                load_frags(cur ^ 1, A0 + ns, B0 + ns);
            }
#pragma unroll
            for (int g = 0; g < 4; g++)
#pragma unroll
                for (int mt = 0; mt < 4; mt++) {
                    mma8(acc[g][mt][0], af[cur][mt], bq[cur][g].x, bq[cur][g].y);
                    mma8(acc[g][mt][1], af[cur][mt], bq[cur][g].z, bq[cur][g].w);
                }
        }
        // next chunk starts with its kk=0 frags already in buf (NKK&1)==0
    }

    // -------- fused LSTM epilogue (register-wise across gates) --------
#pragma unroll
    for (int mt = 0; mt < 4; mt++)
#pragma unroll
        for (int h = 0; h < 2; h++) {
            const int b = m0 + warp_m * 64 + mt * 16 + q + 8 * h;
            const float* pc = prev_c + (size_t)b * HDIM;
            float* oh = out + (size_t)b * HDIM;
            float* oc = out + (size_t)(BDIM + b) * HDIM;
#pragma unroll
            for (int nt = 0; nt < 2; nt++) {
                const int n = n0 + warp_n * 16 + nt * 8 + 2 * cid;
                float2 pcv = *(const float2*)(pc + n);
                float hv[2], cv[2];
#pragma unroll
                for (int e = 0; e < 2; e++) {
                    const float gi = acc[0][mt][nt][2 * h + e];
                    const float gf = acc[1][mt][nt][2 * h + e];
                    const float go = acc[2][mt][nt][2 * h + e];
                    const float gc = acc[3][mt][nt][2 * h + e];
                    const float iv = sigmoidf_(gi);
                    const float fv = sigmoidf_(gf);
                    const float ov = sigmoidf_(go);
                    const float ct = tanhf_(gc);
                    const float pcx = (e == 0) ? pcv.x : pcv.y;
                    const float cc = fv * pcx + iv * ct;
                    cv[e] = cc;
                    hv[e] = ov * tanhf_(cc);
                }
                *(float2*)(oh + n) = make_float2(hv[0], hv[1]);
                *(float2*)(oc + n) = make_float2(cv[0], cv[1]);
            }
        }
}

// ---------------- host launch ----------------
extern "C" void kernel_launch(void* const* d_in, const int* in_sizes, int n_in,
                              void* d_out, int out_size) {
    const float* x      = (const float*)d_in[0];
    const float* prev_h = (const float*)d_in[1];
    const float* prev_c = (const float*)d_in[2];
    const float* Wi     = (const float*)d_in[3];
    const float* Wf     = (const float*)d_in[4];
    const float* Wo     = (const float*)d_in[5];
    const float* Wc     = (const float*)d_in[6];
    float* out = (float*)d_out;

    prep_all<<<9216, 256>>>(x, prev_h, Wi, Wf, Wo, Wc);

    static bool attr_set = false;
    if (!attr_set) {
        cudaFuncSetAttribute(lstm_main, cudaFuncAttributeMaxDynamicSharedMemorySize,
                             SMEM_TOTAL);
        attr_set = true;
    }
    dim3 grid(BDIM / MT, HDIM / NG);   // (32, 32); x-fast -> CTAs sharing weights co-resident
    lstm_main<<<grid, NTHR, SMEM_TOTAL>>>(prev_c, out);
    (void)in_sizes; (void)n_in; (void)out_size;
}